// round 7
// baseline (speedup 1.0000x reference)
#include <cuda_runtime.h>

// CRPS over a 16-member ensemble:
//   out = mean_p( (1/N) sum_i |s_i - y|  -  (1/N^2) sum_{i<j} |s_i - s_j| )
// Identity: with v sorted ascending, sum_{i<j}|v_i - v_j| = sum_i (2i-15) v_i.
//
// R7: cp.async (LDGSTS) smem staging. Register-MLP attempts (R2/R4/R5) all
// failed because ptxas re-serializes loads under its reg budget; cp.async has
// no destination register, so outstanding-load count is decoupled from the
// allocator. Each block double-buffers two 17KB tiles; prefetch of tile 1 is
// in flight while tile 0 computes. Math = R3's sort network (beat pairwise in
// the controlled R3-vs-R6 A/B). Single launch, deterministic fused reduction.

#define NS 16
#define PIXELS (4 * 1 * 256 * 256)      // 262144
#define TPB 256
#define TILE 256                        // pixels per tile
#define TPB_TILES 2                     // tiles per block
#define NBLOCKS (PIXELS / (TILE * TPB_TILES))   // 512
#define TILE_WORDS (NS * TILE + TILE)   // 4352 floats = 17408 B
#define SCHUNKS (NS * TILE / 4)         // 1024 sample 16B-chunks
#define CHUNKS (TILE_WORDS / 4)         // 1088 total 16B-chunks

__device__ float g_partials[NBLOCKS];
__device__ unsigned int g_count = 0;

__device__ __forceinline__ void cmpswap(float& a, float& b) {
    float lo = fminf(a, b);
    float hi = fmaxf(a, b);
    a = lo; b = hi;
}

// Issue one tile's worth of cp.async copies and commit them as one group.
__device__ __forceinline__ void prefetch_tile(
    float* dst, const float* __restrict__ samples,
    const float* __restrict__ target, int tile, int tid)
{
    unsigned dst_base = (unsigned)__cvta_generic_to_shared(dst);
    const int base_px = tile * TILE;
#pragma unroll
    for (int c = tid; c < CHUNKS; c += TPB) {
        const float* src;
        int dst_word;
        if (c < SCHUNKS) {                   // sample rows: 64 chunks per row
            int row = c >> 6;
            int col = (c & 63) << 2;
            src = samples + row * PIXELS + base_px + col;
            dst_word = row * TILE + col;
        } else {                             // target row
            int col = (c - SCHUNKS) << 2;
            src = target + base_px + col;
            dst_word = NS * TILE + col;
        }
        asm volatile("cp.async.cg.shared.global [%0], [%1], 16;"
                     :: "r"(dst_base + dst_word * 4), "l"(src));
    }
    asm volatile("cp.async.commit_group;" ::: "memory");
}

// Per-pixel CRPS contribution from a smem tile.
__device__ __forceinline__ float crps_from_tile(const float* buf, int tid) {
    float v[NS];
#pragma unroll
    for (int i = 0; i < NS; i++)
        v[i] = buf[i * TILE + tid];
    const float y = buf[NS * TILE + tid];

    float t1 = 0.f;
#pragma unroll
    for (int i = 0; i < NS; i++)
        t1 += fabsf(v[i] - y);

    // Batcher odd-even mergesort, 16 inputs, 63 comparators.
#define CS(a, b) cmpswap(v[a], v[b])
    CS(0,1);  CS(2,3);  CS(4,5);  CS(6,7);  CS(8,9);  CS(10,11); CS(12,13); CS(14,15);
    CS(0,2);  CS(1,3);  CS(4,6);  CS(5,7);  CS(8,10); CS(9,11);  CS(12,14); CS(13,15);
    CS(1,2);  CS(5,6);  CS(9,10); CS(13,14);
    CS(0,4);  CS(1,5);  CS(2,6);  CS(3,7);  CS(8,12); CS(9,13);  CS(10,14); CS(11,15);
    CS(2,4);  CS(3,5);  CS(10,12); CS(11,13);
    CS(1,2);  CS(3,4);  CS(5,6);  CS(9,10); CS(11,12); CS(13,14);
    CS(0,8);  CS(1,9);  CS(2,10); CS(3,11); CS(4,12); CS(5,13);  CS(6,14);  CS(7,15);
    CS(4,8);  CS(5,9);  CS(6,10); CS(7,11);
    CS(2,4);  CS(3,5);  CS(6,8);  CS(7,9);  CS(10,12); CS(11,13);
    CS(1,2);  CS(3,4);  CS(5,6);  CS(7,8);  CS(9,10);  CS(11,12); CS(13,14);
#undef CS

    float t2 = 0.f;
#pragma unroll
    for (int i = 0; i < NS; i++)
        t2 = fmaf((float)(2 * i - 15), v[i], t2);

    return t1 * (1.f / NS) - t2 * (1.f / (NS * NS));
}

__global__ __launch_bounds__(TPB) void crps_fused_kernel(
    const float* __restrict__ samples,   // [NS, PIXELS]
    const float* __restrict__ target,    // [PIXELS]
    float* __restrict__ out)
{
    __shared__ float sbuf[2][TILE_WORDS];     // 34,816 B double buffer
    const int tid = threadIdx.x;
    const int tile0 = blockIdx.x * TPB_TILES;

    // Post both tile prefetches up front — all bytes in flight immediately.
    prefetch_tile(sbuf[0], samples, target, tile0,     tid);
    prefetch_tile(sbuf[1], samples, target, tile0 + 1, tid);

    asm volatile("cp.async.wait_group 1;" ::: "memory");
    __syncthreads();
    float acc = crps_from_tile(sbuf[0], tid);

    asm volatile("cp.async.wait_group 0;" ::: "memory");
    __syncthreads();
    acc += crps_from_tile(sbuf[1], tid);

    // ---- block reduction ----
#pragma unroll
    for (int off = 16; off > 0; off >>= 1)
        acc += __shfl_down_sync(0xFFFFFFFFu, acc, off);

    __shared__ float warp_sums[TPB / 32];
    const int lane = tid & 31;
    const int wid  = tid >> 5;
    if (lane == 0) warp_sums[wid] = acc;
    __syncthreads();

    __shared__ bool is_last;
    if (tid == 0) {
        float bsum = 0.f;
#pragma unroll
        for (int w = 0; w < TPB / 32; w++)
            bsum += warp_sums[w];
        g_partials[blockIdx.x] = bsum;
        __threadfence();
        unsigned int done = atomicAdd(&g_count, 1u);
        is_last = (done == NBLOCKS - 1);
    }
    __syncthreads();

    // ---- last block folds all 512 partials in a fixed order ----
    if (is_last) {
        float s = g_partials[tid] + g_partials[tid + TPB];
#pragma unroll
        for (int off = 16; off > 0; off >>= 1)
            s += __shfl_down_sync(0xFFFFFFFFu, s, off);
        if (lane == 0) warp_sums[wid] = s;
        __syncthreads();
        if (wid == 0) {
            float tot = (lane < TPB / 32) ? warp_sums[lane] : 0.f;
#pragma unroll
            for (int off = 4; off > 0; off >>= 1)
                tot += __shfl_down_sync(0xFFFFFFFFu, tot, off);
            if (lane == 0) {
                out[0] = tot * (1.f / PIXELS);
                g_count = 0;   // reset for next graph replay
            }
        }
    }
}

extern "C" void kernel_launch(void* const* d_in, const int* in_sizes, int n_in,
                              void* d_out, int out_size)
{
    const float* samples = (const float*)d_in[0];
    const float* target  = (const float*)d_in[1];
    float* out = (float*)d_out;

    crps_fused_kernel<<<NBLOCKS, TPB>>>(samples, target, out);
}

// round 9
// speedup vs baseline: 1.2536x; 1.2536x over previous
#include <cuda_runtime.h>

// CRPS over a 16-member ensemble:
//   out = mean_p( (1/N) sum_i |s_i - y|  -  (1/N^2) sum_{i<j} |s_i - s_j| )
// Identity: with v sorted ascending, sum_{i<j}|v_i - v_j| = sum_i (2i-15) v_i.
//
// R8: R3 config (best measured: 8.29us kernel) with ONE change:
// __launch_bounds__(256, 4) raises the ptxas register budget 32 -> 64.
// Every previous MLP attempt failed with regs pinned at 32-40 because the
// occupancy-targeting allocator re-serialized the 16-member load batch to
// recycle registers (asm volatile fixes order, not budget). 64 regs lets all
// 16 loads stay live -> true MLP=17/warp. 32 warps/SM residency is plenty.

#define NS 16
#define PIXELS (4 * 1 * 256 * 256)      // 262144
#define TPB 256
#define MINBLK 4                        // -> 64-reg budget
#define NBLOCKS (PIXELS / TPB)          // 1024

__device__ float g_partials[NBLOCKS];
__device__ unsigned int g_count = 0;

__device__ __forceinline__ void cmpswap(float& a, float& b) {
    float lo = fminf(a, b);
    float hi = fmaxf(a, b);
    a = lo; b = hi;
}

__global__ __launch_bounds__(TPB, MINBLK) void crps_fused_kernel(
    const float* __restrict__ samples,   // [NS, PIXELS]
    const float* __restrict__ target,    // [PIXELS]
    float* __restrict__ out)
{
    const int p = blockIdx.x * TPB + threadIdx.x;

    // All 17 loads batched; with a 64-reg budget ptxas keeps them live.
    float v[NS];
#pragma unroll
    for (int i = 0; i < NS; i++)
        v[i] = samples[i * PIXELS + p];
    const float y = target[p];

    // term1: sum_i |v_i - y|  (fma pipe)
    float t1 = 0.f;
#pragma unroll
    for (int i = 0; i < NS; i++)
        t1 += fabsf(v[i] - y);

    // Sort v ascending: Batcher odd-even mergesort, 16 inputs, 63 comparators
    // (126 FMNMX on the alu pipe; overlaps term1's fma-pipe work).
#define CS(a, b) cmpswap(v[a], v[b])
    CS(0,1);  CS(2,3);  CS(4,5);  CS(6,7);  CS(8,9);  CS(10,11); CS(12,13); CS(14,15);
    CS(0,2);  CS(1,3);  CS(4,6);  CS(5,7);  CS(8,10); CS(9,11);  CS(12,14); CS(13,15);
    CS(1,2);  CS(5,6);  CS(9,10); CS(13,14);
    CS(0,4);  CS(1,5);  CS(2,6);  CS(3,7);  CS(8,12); CS(9,13);  CS(10,14); CS(11,15);
    CS(2,4);  CS(3,5);  CS(10,12); CS(11,13);
    CS(1,2);  CS(3,4);  CS(5,6);  CS(9,10); CS(11,12); CS(13,14);
    CS(0,8);  CS(1,9);  CS(2,10); CS(3,11); CS(4,12); CS(5,13);  CS(6,14);  CS(7,15);
    CS(4,8);  CS(5,9);  CS(6,10); CS(7,11);
    CS(2,4);  CS(3,5);  CS(6,8);  CS(7,9);  CS(10,12); CS(11,13);
    CS(1,2);  CS(3,4);  CS(5,6);  CS(7,8);  CS(9,10);  CS(11,12); CS(13,14);
#undef CS

    // term2: sum_{i<j}(v_j - v_i) = sum_i (2i-15) v_i   (16 FFMA)
    float t2 = 0.f;
#pragma unroll
    for (int i = 0; i < NS; i++)
        t2 = fmaf((float)(2 * i - 15), v[i], t2);

    float acc = t1 * (1.f / NS) - t2 * (1.f / (NS * NS));

    // ---- block reduction ----
#pragma unroll
    for (int off = 16; off > 0; off >>= 1)
        acc += __shfl_down_sync(0xFFFFFFFFu, acc, off);

    __shared__ float warp_sums[TPB / 32];
    const int lane = threadIdx.x & 31;
    const int wid  = threadIdx.x >> 5;
    if (lane == 0) warp_sums[wid] = acc;
    __syncthreads();

    __shared__ bool is_last;
    if (threadIdx.x == 0) {
        float bsum = 0.f;
#pragma unroll
        for (int w = 0; w < TPB / 32; w++)
            bsum += warp_sums[w];
        g_partials[blockIdx.x] = bsum;
        __threadfence();
        unsigned int done = atomicAdd(&g_count, 1u);
        is_last = (done == NBLOCKS - 1);
    }
    __syncthreads();

    // ---- last block folds all 1024 partials in a fixed order ----
    if (is_last) {
        float s = 0.f;
#pragma unroll
        for (int k = 0; k < NBLOCKS / TPB; k++)
            s += g_partials[k * TPB + threadIdx.x];
#pragma unroll
        for (int off = 16; off > 0; off >>= 1)
            s += __shfl_down_sync(0xFFFFFFFFu, s, off);
        if (lane == 0) warp_sums[wid] = s;
        __syncthreads();
        if (wid == 0) {
            float tot = (lane < TPB / 32) ? warp_sums[lane] : 0.f;
#pragma unroll
            for (int off = 4; off > 0; off >>= 1)
                tot += __shfl_down_sync(0xFFFFFFFFu, tot, off);
            if (lane == 0) {
                out[0] = tot * (1.f / PIXELS);
                g_count = 0;   // reset for next graph replay
            }
        }
    }
}

extern "C" void kernel_launch(void* const* d_in, const int* in_sizes, int n_in,
                              void* d_out, int out_size)
{
    const float* samples = (const float*)d_in[0];
    const float* target  = (const float*)d_in[1];
    float* out = (float*)d_out;

    crps_fused_kernel<<<NBLOCKS, TPB>>>(samples, target, out);
}